// round 12
// baseline (speedup 1.0000x reference)
#include <cuda_runtime.h>
#include <cuda_fp16.h>
#include <cstdint>

#define NU 30000
#define NI 30000
#define NN 60000
#define NRELS 10
#define NBAS 8
#define DIM 128
#define D4 32
#define NEDGE 1000000
#define NBATCH 256
#define SEQL 50
#define RSLOT 24            // slots per (user, rel); Poisson(3.3) tail @24 ~1e-12
#define USLOT (NRELS * RSLOT)
#define SLOTS 96            // item-side guard (mean 33)

// ---------------- device scratch (static, no runtime alloc) ----------------
__device__ __half  g_WitemH[(size_t)NRELS * NI * DIM];  // fp16 message table ~77MB
__device__ __half  g_socialH[(size_t)NU * DIM];         // fp16 social ~7.7MB (L2-resident)
__device__ float4  g_pooled[NI * D4];                   // fp32 (it IS the h output) ~15MB
__device__ float   g_ei[NI];                            // per-item attention score
__device__ unsigned long long g_packA[NU];              // ten 6-bit per-rel counters
__device__ int     g_pcnt[NI];
__device__ int     g_need[NI];
__device__ int     g_list[NI];
__device__ int     g_nlist;
__device__ int     g_slotA[NU * USLOT];   // rel-major per-user item lists
__device__ int     g_slotB[NI * SLOTS];   // per-needed-item dst lists

__device__ __forceinline__ int sum6(unsigned long long v) {
    int s = 0;
#pragma unroll
    for (int r = 0; r < NRELS; r++) s += (int)((v >> (6 * r)) & 63ULL);
    return s;
}

// ---------------- K0: zero counters ----------------
__global__ void k_zero() {
    int i = blockIdx.x * 256 + threadIdx.x;
    if (i < NU) g_packA[i] = 0ULL;
    if (i < NI) { g_pcnt[i] = 0; g_need[i] = 0; }
    if (i == 0) g_nlist = 0;
}

// ---------------- K0b: mark needed items + compact list ----------------
__global__ void k_flag(const int* __restrict__ ctx) {
    int i = blockIdx.x * 256 + threadIdx.x;
    if (i >= NBATCH * SEQL) return;
    int id = __ldg(ctx + i);
    if (id >= NU && id < NN) {
        int si = id - NU;
        if (atomicExch(&g_need[si], 1) == 0) {
            int p = atomicAdd(&g_nlist, 1);
            g_list[p] = si;
        }
    }
}

// ---------------- K1: rel-major slot append; counter field IS the slot index ----------------
__global__ void k_append(const int* __restrict__ esrc, const int* __restrict__ edst,
                         const int* __restrict__ etyp) {
    int e = blockIdx.x * 256 + threadIdx.x;
    if (e >= NEDGE) return;
    int dst = __ldcs(edst + e), rel = __ldcs(etyp + e), si = __ldcs(esrc + e) - NU;
    if ((unsigned)dst < NU && (unsigned)rel < NRELS && (unsigned)si < NI) {
        unsigned long long old = atomicAdd(&g_packA[dst], 1ULL << (6 * rel));
        int c = (int)((old >> (6 * rel)) & 63ULL);
        if (c < RSLOT) g_slotA[dst * USLOT + rel * RSLOT + c] = si;
    }
    if ((unsigned)si < NI && g_need[si]) {
        int c = atomicAdd(&g_pcnt[si], 1);
        if (c < SLOTS) g_slotB[si * SLOTS + c] = dst;
    }
}

// ---------------- Witem (fp16): warp per item; basis streamed (evict-first) ----------------
__global__ void k_witem(const float* __restrict__ basis, const float* __restrict__ comp) {
    __shared__ float sc[NRELS * NBAS];
    if (threadIdx.x < NRELS * NBAS) sc[threadIdx.x] = comp[threadIdx.x];
    __syncthreads();
    int w = (blockIdx.x * blockDim.x + threadIdx.x) >> 5;
    int lane = threadIdx.x & 31;
    if (w >= NI) return;
    const float4* b4 = (const float4*)basis;
    float4 vb[NBAS];
#pragma unroll
    for (int b = 0; b < NBAS; b++)
        vb[b] = __ldcs(&b4[((size_t)b * NN + NU + w) * D4 + lane]);   // streaming: protect L2
#pragma unroll
    for (int r = 0; r < NRELS; r++) {
        float4 a = make_float4(0.f, 0.f, 0.f, 0.f);
#pragma unroll
        for (int b = 0; b < NBAS; b++) {
            float c = sc[r * NBAS + b];
            a.x += c * vb[b].x; a.y += c * vb[b].y;
            a.z += c * vb[b].z; a.w += c * vb[b].w;
        }
        __half2 h0 = __floats2half2_rn(a.x, a.y);
        __half2 h1 = __floats2half2_rn(a.z, a.w);
        uint2 u = make_uint2(*(uint32_t*)&h0, *(uint32_t*)&h1);
        *(uint2*)(g_WitemH + ((size_t)r * NI + w) * DIM + lane * 4) = u;
    }
}

// ---------------- social: warp per user, REL-PARTITIONED (slab-resident gathers) ----------------
__global__ void __launch_bounds__(256) k_social_dst(const float* __restrict__ root,
                                                    const float* __restrict__ bias) {
    int d = (blockIdx.x * blockDim.x + threadIdx.x) >> 5;
    int lane = threadIdx.x & 31;
    if (d >= NU) return;
    unsigned long long packed = g_packA[d];
    const int* slots = g_slotA + d * USLOT;
    float ax = 0.f, ay = 0.f, az = 0.f, aw = 0.f;
#pragma unroll
    for (int r = 0; r < NRELS; r++) {
        int cr = (int)((packed >> (6 * r)) & 63ULL);
        if (cr == 0) continue;
        int m = min(cr, RSLOT);
        int si = (lane < m) ? __ldg(slots + r * RSLOT + lane) : 0;
        const __half* slab = g_WitemH + (size_t)r * NI * DIM;
        float sx = 0.f, sy = 0.f, sz = 0.f, sw = 0.f;
        int k = 0;
        for (; k + 8 <= m; k += 8) {
            uint2 u[8];
#pragma unroll
            for (int j = 0; j < 8; j++) {
                int s = __shfl_sync(0xffffffffu, si, k + j);
                u[j] = __ldg((const uint2*)(slab + (size_t)s * DIM) + lane);
            }
#pragma unroll
            for (int j = 0; j < 8; j++) {
                float2 f0 = __half22float2(*(__half2*)&u[j].x);
                float2 f1 = __half22float2(*(__half2*)&u[j].y);
                sx += f0.x; sy += f0.y; sz += f1.x; sw += f1.y;
            }
        }
        int rem = m - k;
        if (rem > 0) {
            uint2 u[8];
#pragma unroll
            for (int j = 0; j < 8; j++) {
                if (j < rem) {
                    int s = __shfl_sync(0xffffffffu, si, k + j);
                    u[j] = __ldg((const uint2*)(slab + (size_t)s * DIM) + lane);
                } else {
                    int dummy = __shfl_sync(0xffffffffu, si, k);  // keep shfl uniform
                    (void)dummy;
                    u[j] = make_uint2(0u, 0u);
                }
            }
#pragma unroll
            for (int j = 0; j < 8; j++) {
                float2 f0 = __half22float2(*(__half2*)&u[j].x);
                float2 f1 = __half22float2(*(__half2*)&u[j].y);
                sx += f0.x; sy += f0.y; sz += f1.x; sw += f1.y;
            }
        }
        float inv = 1.0f / (float)cr;
        ax += inv * sx; ay += inv * sy; az += inv * sz; aw += inv * sw;
    }
    const float4* r4 = (const float4*)root;
    const float4* b4 = (const float4*)bias;
    float4 rr = __ldg(&r4[d * D4 + lane]);
    float4 bb = __ldg(&b4[lane]);
    __half2 h0 = __floats2half2_rn(ax + rr.x + bb.x, ay + rr.y + bb.y);
    __half2 h1 = __floats2half2_rn(az + rr.z + bb.z, aw + rr.w + bb.w);
    uint2 u = make_uint2(*(uint32_t*)&h0, *(uint32_t*)&h1);
    *(uint2*)(g_socialH + (size_t)d * DIM + lane * 4) = u;
}

// ---------------- pooled + attention score: persistent, warp per needed item ----------------
__global__ void __launch_bounds__(256) k_pooled_attn(const float* __restrict__ attn_a,
                                                     const float* __restrict__ attn_b) {
    extern __shared__ float sA[];   // 64KB: A[d*128+j]
    int tid = threadIdx.x;
    for (int i = tid; i < DIM * DIM; i += 256) sA[i] = attn_a[i];
    __syncthreads();
    int lane = tid & 31, wid = tid >> 5;
    int cnt = g_nlist;
    float4 myb = ((const float4*)attn_b)[lane];
    for (int w = blockIdx.x * 8 + wid; w < cnt; w += gridDim.x * 8) {
        int item = g_list[w];
        int deg = g_pcnt[item];
        int ndeg = min(deg, SLOTS);
        const int* slots = g_slotB + item * SLOTS;
        float4 acc = make_float4(0.f, 0.f, 0.f, 0.f);
        for (int base = 0; base < ndeg; base += 32) {
            int n = min(32, ndeg - base);
            int dd = 0;
            if (lane < n) dd = __ldg(slots + base + lane);
            int k = 0;
            for (; k + 4 <= n; k += 4) {
                int d0 = __shfl_sync(0xffffffffu, dd, k);
                int d1 = __shfl_sync(0xffffffffu, dd, k + 1);
                int d2 = __shfl_sync(0xffffffffu, dd, k + 2);
                int d3 = __shfl_sync(0xffffffffu, dd, k + 3);
                uint2 u0 = __ldg((const uint2*)(g_socialH + (size_t)d0 * DIM) + lane);
                uint2 u1 = __ldg((const uint2*)(g_socialH + (size_t)d1 * DIM) + lane);
                uint2 u2 = __ldg((const uint2*)(g_socialH + (size_t)d2 * DIM) + lane);
                uint2 u3 = __ldg((const uint2*)(g_socialH + (size_t)d3 * DIM) + lane);
                float2 a0 = __half22float2(*(__half2*)&u0.x), b0 = __half22float2(*(__half2*)&u0.y);
                float2 a1 = __half22float2(*(__half2*)&u1.x), b1 = __half22float2(*(__half2*)&u1.y);
                float2 a2 = __half22float2(*(__half2*)&u2.x), b2 = __half22float2(*(__half2*)&u2.y);
                float2 a3 = __half22float2(*(__half2*)&u3.x), b3 = __half22float2(*(__half2*)&u3.y);
                acc.x += a0.x + a1.x + a2.x + a3.x;
                acc.y += a0.y + a1.y + a2.y + a3.y;
                acc.z += b0.x + b1.x + b2.x + b3.x;
                acc.w += b0.y + b1.y + b2.y + b3.y;
            }
            for (; k < n; k++) {
                int d0 = __shfl_sync(0xffffffffu, dd, k);
                uint2 u0 = __ldg((const uint2*)(g_socialH + (size_t)d0 * DIM) + lane);
                float2 a0 = __half22float2(*(__half2*)&u0.x), b0 = __half22float2(*(__half2*)&u0.y);
                acc.x += a0.x; acc.y += a0.y; acc.z += b0.x; acc.w += b0.y;
            }
        }
        float inv = 1.0f / (float)max(deg, 1);
        acc.x *= inv; acc.y *= inv; acc.z *= inv; acc.w *= inv;
        g_pooled[item * D4 + lane] = acc;
        // ---- score: s[j] = sum_d p[d]*A[d,j]; e = sum_j tanh(s[j])*b[j] ----
        float s0 = 0.f, s1 = 0.f, s2 = 0.f, s3 = 0.f;   // j = 4*lane..+3
        for (int sl = 0; sl < 32; sl++) {
            float px = __shfl_sync(0xffffffffu, acc.x, sl);
            float py = __shfl_sync(0xffffffffu, acc.y, sl);
            float pz = __shfl_sync(0xffffffffu, acc.z, sl);
            float pw = __shfl_sync(0xffffffffu, acc.w, sl);
            const float4* arow = (const float4*)(sA + (4 * sl) * DIM) + lane;
            float4 A0 = arow[0];
            float4 A1 = arow[D4];
            float4 A2 = arow[2 * D4];
            float4 A3 = arow[3 * D4];
            s0 += px * A0.x + py * A1.x + pz * A2.x + pw * A3.x;
            s1 += px * A0.y + py * A1.y + pz * A2.y + pw * A3.y;
            s2 += px * A0.z + py * A1.z + pz * A2.z + pw * A3.z;
            s3 += px * A0.w + py * A1.w + pz * A2.w + pw * A3.w;
        }
        float ep = tanhf(s0) * myb.x + tanhf(s1) * myb.y + tanhf(s2) * myb.z + tanhf(s3) * myb.w;
#pragma unroll
        for (int o = 16; o; o >>= 1) ep += __shfl_down_sync(0xffffffffu, ep, o);
        if (lane == 0) g_ei[item] = ep;
    }
}

// ---------------- final: scores gather, softmax, h write, rep, fc1->fc2 ----------------
__global__ void __launch_bounds__(128) k_final(const int* __restrict__ ctx,
                                               const float* __restrict__ fc1w,
                                               const float* __restrict__ fc1b,
                                               const float* __restrict__ fc2w,
                                               const float* __restrict__ fc2b,
                                               float* __restrict__ proj,
                                               float* __restrict__ hout) {
    int b = blockIdx.x, t = threadIdx.x;
    __shared__ float se[SEQL];
    __shared__ float sw[SEQL];
    __shared__ int   sid[SEQL];     // item index or -1
    __shared__ float srep[DIM];
    __shared__ float sx[DIM];
    if (t < SEQL) {
        int id = ctx[b * SEQL + t];
        bool valid = (id >= NU) && (id < NN);
        int si = valid ? (id - NU) : 0;
        valid = valid && (g_pcnt[si] > 0);
        sid[t] = valid ? si : -1;
        se[t] = valid ? g_ei[si] : -1e9f;
    }
    __syncthreads();
    float m = -3e38f;
#pragma unroll
    for (int l = 0; l < SEQL; l++) m = fmaxf(m, se[l]);
    if (t < SEQL) {
        float ev = se[t];
        sw[t] = (ev <= -0.5e9f) ? 0.f : expf(ev - m);
    }
    __syncthreads();
    float s = 0.f;
#pragma unroll
    for (int l = 0; l < SEQL; l++) s += sw[l];
    float invs = (s > 0.f) ? 1.f / s : 0.f;
    const float* pooled = (const float*)g_pooled;
    float r = 0.f;
#pragma unroll 2
    for (int l = 0; l < SEQL; l++) {
        int si = sid[l];
        float hv = (si >= 0) ? pooled[(size_t)si * DIM + t] : 0.f;
        __stcs(&hout[(b * SEQL + l) * DIM + t], hv);   // streamed out, never re-read
        r += (sw[l] * invs) * hv;
    }
    srep[t] = r;
    __syncthreads();
    float x = fc1b[t];
#pragma unroll 8
    for (int d = 0; d < DIM; d++) x += srep[d] * fc1w[t * DIM + d];
    x = fmaxf(x, 0.f);
    sx[t] = x;
    __syncthreads();
    float p = fc2b[t];
#pragma unroll 8
    for (int d = 0; d < DIM; d++) p += sx[d] * fc2w[t * DIM + d];
    proj[b * DIM + t] = fmaxf(p, 0.f);
}

// ---------------- launch ----------------
extern "C" void kernel_launch(void* const* d_in, const int* in_sizes, int n_in,
                              void* d_out, int out_size) {
    const int*   ctx    = (const int*)d_in[0];
    const int*   esrc   = (const int*)d_in[1];
    const int*   edst   = (const int*)d_in[2];
    const int*   etyp   = (const int*)d_in[3];
    const float* basis  = (const float*)d_in[4];
    const float* comp   = (const float*)d_in[5];
    const float* root   = (const float*)d_in[6];
    const float* bias   = (const float*)d_in[7];
    const float* attn_a = (const float*)d_in[8];
    const float* attn_b = (const float*)d_in[9];
    const float* fc1w   = (const float*)d_in[10];
    const float* fc1b   = (const float*)d_in[11];
    const float* fc2w   = (const float*)d_in[12];
    const float* fc2b   = (const float*)d_in[13];

    float* proj = (float*)d_out;
    float* hout = proj + NBATCH * DIM;

    static cudaStream_t s2 = nullptr;
    static cudaEvent_t evFork = nullptr, evJoin = nullptr;
    if (!s2) {
        cudaStreamCreateWithFlags(&s2, cudaStreamNonBlocking);
        cudaEventCreateWithFlags(&evFork, cudaEventDisableTiming);
        cudaEventCreateWithFlags(&evJoin, cudaEventDisableTiming);
        cudaFuncSetAttribute(k_pooled_attn, cudaFuncAttributeMaxDynamicSharedMemorySize,
                             DIM * DIM * (int)sizeof(float));
    }

    // fork: witem (DRAM-streaming) runs concurrently with the grouping chain
    cudaEventRecord(evFork, 0);
    cudaStreamWaitEvent(s2, evFork, 0);
    k_witem<<<(NI * 32 + 255) / 256, 256, 0, s2>>>(basis, comp);
    cudaEventRecord(evJoin, s2);

    k_zero<<<(NU + 255) / 256, 256>>>();
    k_flag<<<(NBATCH * SEQL + 255) / 256, 256>>>(ctx);
    k_append<<<(NEDGE + 255) / 256, 256>>>(esrc, edst, etyp);

    // join: social needs both the slot table and the Witem table
    cudaStreamWaitEvent(0, evJoin, 0);
    k_social_dst<<<(NU * 32 + 255) / 256, 256>>>(root, bias);
    k_pooled_attn<<<256, 256, DIM * DIM * (int)sizeof(float)>>>(attn_a, attn_b);
    k_final<<<NBATCH, 128>>>(ctx, fc1w, fc1b, fc2w, fc2b, proj, hout);
}

// round 15
// speedup vs baseline: 1.1525x; 1.1525x over previous
#include <cuda_runtime.h>
#include <cuda_fp16.h>
#include <cstdint>

#define NU 30000
#define NI 30000
#define NN 60000
#define NRELS 10
#define NBAS 8
#define DIM 128
#define D4 32
#define NEDGE 1000000
#define NBATCH 256
#define SEQL 50
#define SLOTS 96            // max degree guard (mean 33, sigma 5.8)

// ---------------- device scratch (static, no runtime alloc) ----------------
__device__ __half  g_WitemH[(size_t)NRELS * NI * DIM];  // fp16 message table ~77MB
__device__ __half  g_socialH[(size_t)NU * DIM];         // fp16 social ~7.7MB (L2-resident)
__device__ float4  g_pooled[NI * D4];                   // fp32 (it IS the h output) ~15MB
__device__ float   g_ei[NI];                            // per-item attention score
__device__ unsigned long long g_packA[NU];              // ten 6-bit per-rel counters
__device__ int     g_pcnt[NI];
__device__ int     g_need[NI];
__device__ int     g_list[NI];
__device__ int     g_nlist;
__device__ int     g_slotA[NU * SLOTS];   // per-user edge records (rel<<15)|si
__device__ int     g_slotB[NI * SLOTS];   // per-needed-item dst lists

__device__ __forceinline__ int sum6(unsigned long long v) {
    int s = 0;
#pragma unroll
    for (int r = 0; r < NRELS; r++) s += (int)((v >> (6 * r)) & 63ULL);
    return s;
}

// evict-last gather via cache-policy operand (valid for any width, unlike the
// immediate .L2::evict_last qualifier which ptxas restricts to 32B vectors)
__device__ __forceinline__ unsigned long long mk_policy() {
    unsigned long long pol;
    asm("createpolicy.fractional.L2::evict_last.b64 %0, 1.0;" : "=l"(pol));
    return pol;
}
__device__ __forceinline__ uint2 ldg_keep(const uint2* p, unsigned long long pol) {
    uint2 v;
    asm volatile("ld.global.nc.L2::cache_hint.v2.u32 {%0,%1}, [%2], %3;"
                 : "=r"(v.x), "=r"(v.y) : "l"(p), "l"(pol));
    return v;
}

// ---------------- tail: zero counters for the NEXT replay ----------------
// Statics begin zero-initialized (first/correctness call sees clean state);
// every replay ends by re-zeroing -> deterministic across replays.
__global__ void k_zero_tail() {
    int i = blockIdx.x * 256 + threadIdx.x;
    if (i < NU) g_packA[i] = 0ULL;
    if (i < NI) { g_pcnt[i] = 0; g_need[i] = 0; }
    if (i == 0) g_nlist = 0;
}

// ---------------- mark needed items + compact list ----------------
__global__ void k_flag(const int* __restrict__ ctx) {
    int i = blockIdx.x * 256 + threadIdx.x;
    if (i >= NBATCH * SEQL) return;
    int id = __ldg(ctx + i);
    if (id >= NU && id < NN) {
        int si = id - NU;
        if (atomicExch(&g_need[si], 1) == 0) {
            int p = atomicAdd(&g_nlist, 1);
            g_list[p] = si;
        }
    }
}

// ---------------- slot append; packed 64-bit atomic gives slot + rel counts ----------------
__global__ void k_append(const int* __restrict__ esrc, const int* __restrict__ edst,
                         const int* __restrict__ etyp) {
    int e = blockIdx.x * 256 + threadIdx.x;
    if (e >= NEDGE) return;
    int dst = __ldcs(edst + e), rel = __ldcs(etyp + e), si = __ldcs(esrc + e) - NU;
    if ((unsigned)dst < NU && (unsigned)rel < NRELS && (unsigned)si < NI) {
        unsigned long long old = atomicAdd(&g_packA[dst], 1ULL << (6 * rel));
        int c = sum6(old);
        if (c < SLOTS) g_slotA[dst * SLOTS + c] = (rel << 15) | si;
    }
    if ((unsigned)si < NI && g_need[si]) {
        int c = atomicAdd(&g_pcnt[si], 1);
        if (c < SLOTS) g_slotB[si * SLOTS + c] = dst;
    }
}

// ---------------- Witem (fp16): warp per item; basis streamed (evict-first) ----------------
__global__ void k_witem(const float* __restrict__ basis, const float* __restrict__ comp) {
    __shared__ float sc[NRELS * NBAS];
    if (threadIdx.x < NRELS * NBAS) sc[threadIdx.x] = comp[threadIdx.x];
    __syncthreads();
    int w = (blockIdx.x * blockDim.x + threadIdx.x) >> 5;
    int lane = threadIdx.x & 31;
    if (w >= NI) return;
    const float4* b4 = (const float4*)basis;
    float4 vb[NBAS];
#pragma unroll
    for (int b = 0; b < NBAS; b++)
        vb[b] = __ldcs(&b4[((size_t)b * NN + NU + w) * D4 + lane]);   // streaming: protect L2
#pragma unroll
    for (int r = 0; r < NRELS; r++) {
        float4 a = make_float4(0.f, 0.f, 0.f, 0.f);
#pragma unroll
        for (int b = 0; b < NBAS; b++) {
            float c = sc[r * NBAS + b];
            a.x += c * vb[b].x; a.y += c * vb[b].y;
            a.z += c * vb[b].z; a.w += c * vb[b].w;
        }
        __half2 h0 = __floats2half2_rn(a.x, a.y);
        __half2 h1 = __floats2half2_rn(a.z, a.w);
        uint2 u = make_uint2(*(uint32_t*)&h0, *(uint32_t*)&h1);
        *(uint2*)(g_WitemH + ((size_t)r * NI + w) * DIM + lane * 4) = u;
    }
}

// ---------------- social: warp per user; single pass; evict-last gathers ----------------
__global__ void __launch_bounds__(256) k_social_dst(const float* __restrict__ root,
                                                    const float* __restrict__ bias) {
    __shared__ float sinv[8][16];
    int d = (blockIdx.x * blockDim.x + threadIdx.x) >> 5;
    int lane = threadIdx.x & 31;
    int wid = (threadIdx.x >> 5) & 7;
    if (d >= NU) return;
    unsigned long long pol = mk_policy();
    unsigned long long packed = g_packA[d];          // broadcast load
    int cnt = min(sum6(packed), SLOTS);
    if (lane < NRELS) {
        int cr = (int)((packed >> (6 * lane)) & 63ULL);
        sinv[wid][lane] = 1.0f / (float)max(cr, 1);
    }
    __syncwarp();
    const int* slots = g_slotA + d * SLOTS;
    float ax = 0.f, ay = 0.f, az = 0.f, aw = 0.f;
    for (int base = 0; base < cnt; base += 32) {
        int n = min(32, cnt - base);
        int packedrec = 0; float inv = 0.f;
        if (lane < n) {
            packedrec = __ldcs(slots + base + lane);
            inv = sinv[wid][packedrec >> 15];
        }
        int k = 0;
        for (; k + 8 <= n; k += 8) {
            uint2 u[8]; float iv[8];
#pragma unroll
            for (int j = 0; j < 8; j++) {
                int p = __shfl_sync(0xffffffffu, packedrec, k + j);
                iv[j] = __shfl_sync(0xffffffffu, inv, k + j);
                const uint2* row = (const uint2*)(g_WitemH +
                    ((size_t)(p >> 15) * NI + (p & 32767)) * DIM);
                u[j] = ldg_keep(row + lane, pol);  // 8 independent gathers, evict-last
            }
#pragma unroll
            for (int j = 0; j < 8; j++) {
                float2 f0 = __half22float2(*(__half2*)&u[j].x);
                float2 f1 = __half22float2(*(__half2*)&u[j].y);
                ax += iv[j] * f0.x; ay += iv[j] * f0.y;
                az += iv[j] * f1.x; aw += iv[j] * f1.y;
            }
        }
        for (; k < n; k++) {
            int p = __shfl_sync(0xffffffffu, packedrec, k);
            float ivv = __shfl_sync(0xffffffffu, inv, k);
            const uint2* row = (const uint2*)(g_WitemH +
                ((size_t)(p >> 15) * NI + (p & 32767)) * DIM);
            uint2 u = ldg_keep(row + lane, pol);
            float2 f0 = __half22float2(*(__half2*)&u.x);
            float2 f1 = __half22float2(*(__half2*)&u.y);
            ax += ivv * f0.x; ay += ivv * f0.y; az += ivv * f1.x; aw += ivv * f1.y;
        }
    }
    const float4* r4 = (const float4*)root;
    const float4* b4 = (const float4*)bias;
    float4 rr = __ldg(&r4[d * D4 + lane]);
    float4 bb = __ldg(&b4[lane]);
    __half2 h0 = __floats2half2_rn(ax + rr.x + bb.x, ay + rr.y + bb.y);
    __half2 h1 = __floats2half2_rn(az + rr.z + bb.z, aw + rr.w + bb.w);
    uint2 u = make_uint2(*(uint32_t*)&h0, *(uint32_t*)&h1);
    *(uint2*)(g_socialH + (size_t)d * DIM + lane * 4) = u;
}

// ---------------- pooled + attention score: persistent, warp per needed item ----------------
__global__ void __launch_bounds__(256) k_pooled_attn(const float* __restrict__ attn_a,
                                                     const float* __restrict__ attn_b) {
    extern __shared__ float sA[];   // 64KB: A[d*128+j]
    int tid = threadIdx.x;
    for (int i = tid; i < DIM * DIM; i += 256) sA[i] = attn_a[i];
    __syncthreads();
    int lane = tid & 31, wid = tid >> 5;
    int cnt = g_nlist;
    float4 myb = ((const float4*)attn_b)[lane];
    for (int w = blockIdx.x * 8 + wid; w < cnt; w += gridDim.x * 8) {
        int item = g_list[w];
        int deg = g_pcnt[item];
        int ndeg = min(deg, SLOTS);
        const int* slots = g_slotB + item * SLOTS;
        float4 acc = make_float4(0.f, 0.f, 0.f, 0.f);
        for (int base = 0; base < ndeg; base += 32) {
            int n = min(32, ndeg - base);
            int dd = 0;
            if (lane < n) dd = __ldg(slots + base + lane);
            int k = 0;
            for (; k + 4 <= n; k += 4) {
                int d0 = __shfl_sync(0xffffffffu, dd, k);
                int d1 = __shfl_sync(0xffffffffu, dd, k + 1);
                int d2 = __shfl_sync(0xffffffffu, dd, k + 2);
                int d3 = __shfl_sync(0xffffffffu, dd, k + 3);
                uint2 u0 = __ldg((const uint2*)(g_socialH + (size_t)d0 * DIM) + lane);
                uint2 u1 = __ldg((const uint2*)(g_socialH + (size_t)d1 * DIM) + lane);
                uint2 u2 = __ldg((const uint2*)(g_socialH + (size_t)d2 * DIM) + lane);
                uint2 u3 = __ldg((const uint2*)(g_socialH + (size_t)d3 * DIM) + lane);
                float2 a0 = __half22float2(*(__half2*)&u0.x), b0 = __half22float2(*(__half2*)&u0.y);
                float2 a1 = __half22float2(*(__half2*)&u1.x), b1 = __half22float2(*(__half2*)&u1.y);
                float2 a2 = __half22float2(*(__half2*)&u2.x), b2 = __half22float2(*(__half2*)&u2.y);
                float2 a3 = __half22float2(*(__half2*)&u3.x), b3 = __half22float2(*(__half2*)&u3.y);
                acc.x += a0.x + a1.x + a2.x + a3.x;
                acc.y += a0.y + a1.y + a2.y + a3.y;
                acc.z += b0.x + b1.x + b2.x + b3.x;
                acc.w += b0.y + b1.y + b2.y + b3.y;
            }
            for (; k < n; k++) {
                int d0 = __shfl_sync(0xffffffffu, dd, k);
                uint2 u0 = __ldg((const uint2*)(g_socialH + (size_t)d0 * DIM) + lane);
                float2 a0 = __half22float2(*(__half2*)&u0.x), b0 = __half22float2(*(__half2*)&u0.y);
                acc.x += a0.x; acc.y += a0.y; acc.z += b0.x; acc.w += b0.y;
            }
        }
        float inv = 1.0f / (float)max(deg, 1);
        acc.x *= inv; acc.y *= inv; acc.z *= inv; acc.w *= inv;
        g_pooled[item * D4 + lane] = acc;
        // ---- score: s[j] = sum_d p[d]*A[d,j]; e = sum_j tanh(s[j])*b[j] ----
        float s0 = 0.f, s1 = 0.f, s2 = 0.f, s3 = 0.f;   // j = 4*lane..+3
        for (int sl = 0; sl < 32; sl++) {
            float px = __shfl_sync(0xffffffffu, acc.x, sl);
            float py = __shfl_sync(0xffffffffu, acc.y, sl);
            float pz = __shfl_sync(0xffffffffu, acc.z, sl);
            float pw = __shfl_sync(0xffffffffu, acc.w, sl);
            const float4* arow = (const float4*)(sA + (4 * sl) * DIM) + lane;
            float4 A0 = arow[0];
            float4 A1 = arow[D4];
            float4 A2 = arow[2 * D4];
            float4 A3 = arow[3 * D4];
            s0 += px * A0.x + py * A1.x + pz * A2.x + pw * A3.x;
            s1 += px * A0.y + py * A1.y + pz * A2.y + pw * A3.y;
            s2 += px * A0.z + py * A1.z + pz * A2.z + pw * A3.z;
            s3 += px * A0.w + py * A1.w + pz * A2.w + pw * A3.w;
        }
        float ep = tanhf(s0) * myb.x + tanhf(s1) * myb.y + tanhf(s2) * myb.z + tanhf(s3) * myb.w;
#pragma unroll
        for (int o = 16; o; o >>= 1) ep += __shfl_down_sync(0xffffffffu, ep, o);
        if (lane == 0) g_ei[item] = ep;
    }
}

// ---------------- final: scores gather, softmax, h write, rep, fc1->fc2 ----------------
__global__ void __launch_bounds__(128) k_final(const int* __restrict__ ctx,
                                               const float* __restrict__ fc1w,
                                               const float* __restrict__ fc1b,
                                               const float* __restrict__ fc2w,
                                               const float* __restrict__ fc2b,
                                               float* __restrict__ proj,
                                               float* __restrict__ hout) {
    int b = blockIdx.x, t = threadIdx.x;
    __shared__ float se[SEQL];
    __shared__ float sw[SEQL];
    __shared__ int   sid[SEQL];     // item index or -1
    __shared__ float srep[DIM];
    __shared__ float sx[DIM];
    if (t < SEQL) {
        int id = ctx[b * SEQL + t];
        bool valid = (id >= NU) && (id < NN);
        int si = valid ? (id - NU) : 0;
        valid = valid && (g_pcnt[si] > 0);
        sid[t] = valid ? si : -1;
        se[t] = valid ? g_ei[si] : -1e9f;
    }
    __syncthreads();
    float m = -3e38f;
#pragma unroll
    for (int l = 0; l < SEQL; l++) m = fmaxf(m, se[l]);
    if (t < SEQL) {
        float ev = se[t];
        sw[t] = (ev <= -0.5e9f) ? 0.f : expf(ev - m);
    }
    __syncthreads();
    float s = 0.f;
#pragma unroll
    for (int l = 0; l < SEQL; l++) s += sw[l];
    float invs = (s > 0.f) ? 1.f / s : 0.f;
    const float* pooled = (const float*)g_pooled;
    float r = 0.f;
#pragma unroll 2
    for (int l = 0; l < SEQL; l++) {
        int si = sid[l];
        float hv = (si >= 0) ? pooled[(size_t)si * DIM + t] : 0.f;
        __stcs(&hout[(b * SEQL + l) * DIM + t], hv);   // streamed out, never re-read
        r += (sw[l] * invs) * hv;
    }
    srep[t] = r;
    __syncthreads();
    float x = fc1b[t];
#pragma unroll 8
    for (int d = 0; d < DIM; d++) x += srep[d] * fc1w[t * DIM + d];
    x = fmaxf(x, 0.f);
    sx[t] = x;
    __syncthreads();
    float p = fc2b[t];
#pragma unroll 8
    for (int d = 0; d < DIM; d++) p += sx[d] * fc2w[t * DIM + d];
    proj[b * DIM + t] = fmaxf(p, 0.f);
}

// ---------------- launch ----------------
extern "C" void kernel_launch(void* const* d_in, const int* in_sizes, int n_in,
                              void* d_out, int out_size) {
    const int*   ctx    = (const int*)d_in[0];
    const int*   esrc   = (const int*)d_in[1];
    const int*   edst   = (const int*)d_in[2];
    const int*   etyp   = (const int*)d_in[3];
    const float* basis  = (const float*)d_in[4];
    const float* comp   = (const float*)d_in[5];
    const float* root   = (const float*)d_in[6];
    const float* bias   = (const float*)d_in[7];
    const float* attn_a = (const float*)d_in[8];
    const float* attn_b = (const float*)d_in[9];
    const float* fc1w   = (const float*)d_in[10];
    const float* fc1b   = (const float*)d_in[11];
    const float* fc2w   = (const float*)d_in[12];
    const float* fc2b   = (const float*)d_in[13];

    float* proj = (float*)d_out;
    float* hout = proj + NBATCH * DIM;

    static cudaStream_t s2 = nullptr;
    static cudaEvent_t evFork = nullptr, evJoin = nullptr;
    if (!s2) {
        cudaStreamCreateWithFlags(&s2, cudaStreamNonBlocking);
        cudaEventCreateWithFlags(&evFork, cudaEventDisableTiming);
        cudaEventCreateWithFlags(&evJoin, cudaEventDisableTiming);
        cudaFuncSetAttribute(k_pooled_attn, cudaFuncAttributeMaxDynamicSharedMemorySize,
                             DIM * DIM * (int)sizeof(float));
    }

    // fork: witem (DRAM-streaming) runs concurrently with the grouping chain.
    // Counters were zeroed by the previous replay's tail (or static init).
    cudaEventRecord(evFork, 0);
    cudaStreamWaitEvent(s2, evFork, 0);
    k_witem<<<(NI * 32 + 255) / 256, 256, 0, s2>>>(basis, comp);
    cudaEventRecord(evJoin, s2);

    k_flag<<<(NBATCH * SEQL + 255) / 256, 256>>>(ctx);
    k_append<<<(NEDGE + 255) / 256, 256>>>(esrc, edst, etyp);

    // join: social needs both the slot table and the Witem table
    cudaStreamWaitEvent(0, evJoin, 0);
    k_social_dst<<<(NU * 32 + 255) / 256, 256>>>(root, bias);
    k_pooled_attn<<<256, 256, DIM * DIM * (int)sizeof(float)>>>(attn_a, attn_b);
    k_final<<<NBATCH, 128>>>(ctx, fc1w, fc1b, fc2w, fc2b, proj, hout);
    k_zero_tail<<<(NU + 255) / 256, 256>>>();   // reset state for next replay
}